// round 1
// baseline (speedup 1.0000x reference)
#include <cuda_runtime.h>
#include <math.h>

// Problem: 2-layer GATv2 (H=2 heads, C=32 ch) + edge MLP.
// N=50000 nodes, E=800000 edges (+N self loops). Output: E float logits.

#define HC 64
#define CC 32
#define MAXN 65536
#define MAXE 1048576
#define MAXEP (MAXE + MAXN)
#define MAXDEG 512

// ---- device scratch (static, no runtime allocation) ----
__device__ float g_z[MAXN * HC];      // per-layer z = h@W + b
__device__ float g_hA[MAXN * HC];     // hidden after layer 0
__device__ float g_hB[MAXN * HC];     // hidden after layer 1 (final)
__device__ int   g_deg[MAXN];
__device__ int   g_off[MAXN + 1];
__device__ int   g_cur[MAXN];
__device__ int   g_csr[MAXEP];
__device__ float g_u[MAXN * CC];      // h @ Wm1[0:64]
__device__ float g_v[MAXN * CC];      // h @ Wm1[64:128]
__device__ float g_easum[2];
__device__ float g_gc[CC];            // goal @ Wm1[128:192] + bm1

__device__ __forceinline__ float warp_sum(float v) {
#pragma unroll
    for (int o = 16; o; o >>= 1) v += __shfl_xor_sync(0xffffffffu, v, o);
    return v;
}

// ---- preprocessing ----
__global__ void k_zero(int N) {
    int i = blockIdx.x * blockDim.x + threadIdx.x;
    if (i < N) g_deg[i] = 0;
    if (i < 2) g_easum[i] = 0.f;
}

__global__ void k_easum(const float* __restrict__ EA, int E) {
    __shared__ float s0[256], s1[256];
    int tid = threadIdx.x;
    float a0 = 0.f, a1 = 0.f;
    for (int i = blockIdx.x * 256 + tid; i < E; i += gridDim.x * 256) {
        a0 += EA[2 * i];
        a1 += EA[2 * i + 1];
    }
    s0[tid] = a0; s1[tid] = a1;
    __syncthreads();
    for (int s = 128; s; s >>= 1) {
        if (tid < s) { s0[tid] += s0[tid + s]; s1[tid] += s1[tid + s]; }
        __syncthreads();
    }
    if (tid == 0) {
        atomicAdd(&g_easum[0], s0[0]);
        atomicAdd(&g_easum[1], s1[0]);
    }
}

__global__ void k_degree(const int* __restrict__ EI, int E, int EP) {
    int e = blockIdx.x * blockDim.x + threadIdx.x;
    if (e >= EP) return;
    int dst = (e < E) ? EI[E + e] : (e - E);
    atomicAdd(&g_deg[dst], 1);
}

__global__ void k_scan(int N) {
    __shared__ int sh[1024];
    int tid = threadIdx.x;
    int carry = 0;
    for (int base = 0; base < N; base += 1024) {
        int i = base + tid;
        int v = (i < N) ? g_deg[i] : 0;
        sh[tid] = v;
        __syncthreads();
        for (int s = 1; s < 1024; s <<= 1) {
            int t = (tid >= s) ? sh[tid - s] : 0;
            __syncthreads();
            sh[tid] += t;
            __syncthreads();
        }
        if (i < N) {
            int excl = carry + sh[tid] - v;
            g_off[i] = excl;
            g_cur[i] = excl;
        }
        int tot = sh[1023];
        __syncthreads();
        carry += tot;
    }
    if (tid == 0) g_off[N] = carry;
}

__global__ void k_scatter(const int* __restrict__ EI, int E, int EP) {
    int e = blockIdx.x * blockDim.x + threadIdx.x;
    if (e >= EP) return;
    int dst = (e < E) ? EI[E + e] : (e - E);
    int pos = atomicAdd(&g_cur[dst], 1);
    g_csr[pos] = e;
}

// ---- node linears ----
__global__ void k_lin0(const float* __restrict__ x, const float* __restrict__ W0,
                       const float* __restrict__ b0, int N) {
    int i = blockIdx.x * blockDim.x + threadIdx.x;
    if (i >= N * HC) return;
    int n = i >> 6, j = i & 63;
    g_z[i] = fmaf(x[2 * n], W0[j], fmaf(x[2 * n + 1], W0[64 + j], b0[j]));
}

// z = g_hA @ W + b (64x64), warp per node
__global__ void k_lin64(const float* __restrict__ W, const float* __restrict__ b, int N) {
    __shared__ float sh[8][64];
    int gw = (blockIdx.x * blockDim.x + threadIdx.x) >> 5;
    int lane = threadIdx.x & 31;
    int wl = threadIdx.x >> 5;
    if (gw >= N) return;
    sh[wl][lane]      = g_hA[gw * 64 + lane];
    sh[wl][32 + lane] = g_hA[gw * 64 + 32 + lane];
    __syncwarp();
    float a0 = b[lane], a1 = b[32 + lane];
#pragma unroll
    for (int k = 0; k < 64; k++) {
        float hk = sh[wl][k];
        a0 = fmaf(hk, W[k * 64 + lane], a0);
        a1 = fmaf(hk, W[k * 64 + 32 + lane], a1);
    }
    g_z[gw * 64 + lane]      = a0;
    g_z[gw * 64 + 32 + lane] = a1;
}

// ---- fused GATv2 attention + segment softmax + aggregation + ELU ----
// one warp per destination node; reads g_z, writes g_hA (outSel=0) or g_hB (outSel=1)
__global__ void k_gat(const int* __restrict__ EI, const float* __restrict__ EA,
                      const float* __restrict__ We, const float* __restrict__ att,
                      const float* __restrict__ bias, int outSel,
                      int N, int E, float invE) {
    __shared__ float sh0[8][MAXDEG];
    __shared__ float sh1[8][MAXDEG];
    int gw = (blockIdx.x * blockDim.x + threadIdx.x) >> 5;
    int lane = threadIdx.x & 31;
    int wl = threadIdx.x >> 5;
    if (gw >= N) return;
    float* __restrict__ hout = outSel ? g_hB : g_hA;
    int d = gw;
    int off0 = g_off[d];
    int deg = g_off[d + 1] - off0;
    if (deg > MAXDEG) deg = MAXDEG;
    float mean0 = g_easum[0] * invE, mean1 = g_easum[1] * invE;
    float zd0 = g_z[d * 64 + lane], zd1 = g_z[d * 64 + 32 + lane];
    float We0l = We[lane],       We1l = We[64 + lane];
    float We0h = We[32 + lane],  We1h = We[96 + lane];
    float at0 = att[lane], at1 = att[32 + lane];

    // pass A: per-edge attention logits (warp-parallel channel dot), track max
    float m0 = -1e30f, m1 = -1e30f;
    for (int j = 0; j < deg; j++) {
        int e = g_csr[off0 + j];
        int src; float ea0, ea1;
        if (e < E) { src = EI[e]; ea0 = EA[2 * e]; ea1 = EA[2 * e + 1]; }
        else       { src = d;     ea0 = mean0;    ea1 = mean1; }
        float zs0 = g_z[src * 64 + lane], zs1 = g_z[src * 64 + 32 + lane];
        float t0 = zd0 + zs0 + ea0 * We0l + ea1 * We1l;
        float t1 = zd1 + zs1 + ea0 * We0h + ea1 * We1h;
        t0 = (t0 > 0.f) ? t0 : 0.2f * t0;   // leaky relu 0.2
        t1 = (t1 > 0.f) ? t1 : 0.2f * t1;
        float a0 = warp_sum(t0 * at0);
        float a1 = warp_sum(t1 * at1);
        if (lane == 0) { sh0[wl][j] = a0; sh1[wl][j] = a1; }
        m0 = fmaxf(m0, a0);
        m1 = fmaxf(m1, a1);
    }
    __syncwarp();

    // pass B: exp + denom
    float s0 = 0.f, s1 = 0.f;
    for (int j = lane; j < deg; j += 32) {
        float e0 = __expf(sh0[wl][j] - m0); sh0[wl][j] = e0; s0 += e0;
        float e1 = __expf(sh1[wl][j] - m1); sh1[wl][j] = e1; s1 += e1;
    }
    s0 = warp_sum(s0);
    s1 = warp_sum(s1);
    __syncwarp();
    float inv0 = 1.f / (s0 + 1e-16f);
    float inv1 = 1.f / (s1 + 1e-16f);

    // pass C: weighted message aggregation
    float acc0 = 0.f, acc1 = 0.f;
    for (int j = 0; j < deg; j++) {
        int e = g_csr[off0 + j];
        int src = (e < E) ? EI[e] : d;
        float a0 = sh0[wl][j] * inv0;
        float a1 = sh1[wl][j] * inv1;
        acc0 = fmaf(a0, g_z[src * 64 + lane], acc0);
        acc1 = fmaf(a1, g_z[src * 64 + 32 + lane], acc1);
    }
    float o0 = acc0 + bias[lane];
    float o1 = acc1 + bias[32 + lane];
    hout[d * 64 + lane]      = (o0 > 0.f) ? o0 : (__expf(o0) - 1.f);   // elu
    hout[d * 64 + 32 + lane] = (o1 > 0.f) ? o1 : (__expf(o1) - 1.f);
}

// ---- final edge MLP (factored) ----
__global__ void k_uv(const float* __restrict__ Wm1, int N) {
    __shared__ float sh[8][64];
    int gw = (blockIdx.x * blockDim.x + threadIdx.x) >> 5;
    int lane = threadIdx.x & 31;
    int wl = threadIdx.x >> 5;
    if (gw >= N) return;
    sh[wl][lane]      = g_hB[gw * 64 + lane];
    sh[wl][32 + lane] = g_hB[gw * 64 + 32 + lane];
    __syncwarp();
    float au = 0.f, av = 0.f;
#pragma unroll
    for (int k = 0; k < 64; k++) {
        float hk = sh[wl][k];
        au = fmaf(hk, Wm1[k * 32 + lane], au);
        av = fmaf(hk, Wm1[(64 + k) * 32 + lane], av);
    }
    g_u[gw * 32 + lane] = au;
    g_v[gw * 32 + lane] = av;
}

__global__ void k_goal(const float* __restrict__ Wm1, const float* __restrict__ bm1,
                       const int* __restrict__ dest) {
    int lane = threadIdx.x;
    int d = dest[0];
    float acc = bm1[lane];
    for (int k = 0; k < 64; k++)
        acc = fmaf(g_hB[d * 64 + k], Wm1[(128 + k) * 32 + lane], acc);
    g_gc[lane] = acc;
}

__global__ void k_edge(const int* __restrict__ EI, const float* __restrict__ EA,
                       const float* __restrict__ Wm1, const float* __restrict__ Wm2,
                       const float* __restrict__ bm2, float* __restrict__ out, int E) {
    int gw = (blockIdx.x * blockDim.x + threadIdx.x) >> 5;
    int lane = threadIdx.x & 31;
    if (gw >= E) return;
    int src = EI[gw], dst = EI[E + gw];
    float ea0 = EA[2 * gw], ea1 = EA[2 * gw + 1];
    float t = g_u[src * 32 + lane] + g_v[dst * 32 + lane] + g_gc[lane]
            + ea0 * Wm1[192 * 32 + lane] + ea1 * Wm1[193 * 32 + lane];
    t = fmaxf(t, 0.f);
    float p = warp_sum(t * Wm2[lane]);
    if (lane == 0) out[gw] = p + bm2[0];
}

extern "C" void kernel_launch(void* const* d_in, const int* in_sizes, int n_in,
                              void* d_out, int out_size) {
    const float* x     = (const float*)d_in[0];
    const int*   EI    = (const int*)  d_in[1];
    const float* EA    = (const float*)d_in[2];
    const int*   dest  = (const int*)  d_in[3];
    const float* W0    = (const float*)d_in[4];
    const float* b0    = (const float*)d_in[5];
    const float* We0   = (const float*)d_in[6];
    const float* att0  = (const float*)d_in[7];
    const float* bias0 = (const float*)d_in[8];
    const float* W1    = (const float*)d_in[9];
    const float* b1    = (const float*)d_in[10];
    const float* We1   = (const float*)d_in[11];
    const float* att1  = (const float*)d_in[12];
    const float* bias1 = (const float*)d_in[13];
    const float* Wm1   = (const float*)d_in[14];
    const float* bm1   = (const float*)d_in[15];
    const float* Wm2   = (const float*)d_in[16];
    const float* bm2   = (const float*)d_in[17];

    int N  = in_sizes[0] / 2;
    int E  = in_sizes[1] / 2;
    int EP = E + N;
    float invE = 1.0f / (float)E;
    float* out = (float*)d_out;

    // CSR build (dst fixed across layers)
    k_zero   <<<(N + 255) / 256, 256>>>(N);
    k_easum  <<<512, 256>>>(EA, E);
    k_degree <<<(EP + 255) / 256, 256>>>(EI, E, EP);
    k_scan   <<<1, 1024>>>(N);
    k_scatter<<<(EP + 255) / 256, 256>>>(EI, E, EP);

    int gatBlocks = (N + 7) / 8;

    // layer 0
    k_lin0<<<(N * 64 + 255) / 256, 256>>>(x, W0, b0, N);
    k_gat <<<gatBlocks, 256>>>(EI, EA, We0, att0, bias0, /*outSel=*/0, N, E, invE);

    // layer 1
    k_lin64<<<gatBlocks, 256>>>(W1, b1, N);
    k_gat  <<<gatBlocks, 256>>>(EI, EA, We1, att1, bias1, /*outSel=*/1, N, E, invE);

    // edge MLP (factored per-node precomputes)
    k_uv  <<<gatBlocks, 256>>>(Wm1, N);
    k_goal<<<1, 32>>>(Wm1, bm1, dest);
    k_edge<<<(E + 7) / 8, 256>>>(EI, EA, Wm1, Wm2, bm2, out, E);
}

// round 2
// speedup vs baseline: 1.1473x; 1.1473x over previous
#include <cuda_runtime.h>
#include <math.h>

// 2-layer GATv2 (H=2 heads, C=32 ch) + edge MLP.
// N=50000 nodes, E=800000 edges (+N self loops). Output: E float logits.

#define HC 64
#define CC 32
#define MAXN 65536
#define MAXE 1048576
#define MAXEP (MAXE + MAXN)
#define SCANB 1024
#define MAXBLK 64

// ---- device scratch (static) ----
__device__ float  g_z[MAXN * HC];
__device__ float  g_hA[MAXN * HC];
__device__ float  g_hB[MAXN * HC];
__device__ int    g_deg[MAXN];
__device__ int    g_off[MAXN + 1];
__device__ int    g_cur[MAXN];
__device__ int    g_srcOf[MAXEP];
__device__ float2 g_eas[MAXEP];
__device__ int    g_dstOf[MAXEP];
__device__ float2 g_al[MAXEP];
__device__ float  g_u[MAXN * CC];
__device__ float  g_v[MAXN * CC];
__device__ float  g_easum[2];
__device__ float  g_gc[CC];
__device__ int    g_bsum[MAXBLK];
__device__ int    g_bbase[MAXBLK];

__device__ __forceinline__ float warp_sum(float v) {
#pragma unroll
    for (int o = 16; o; o >>= 1) v += __shfl_xor_sync(0xffffffffu, v, o);
    return v;
}
__device__ __forceinline__ float warp_max(float v) {
#pragma unroll
    for (int o = 16; o; o >>= 1) v = fmaxf(v, __shfl_xor_sync(0xffffffffu, v, o));
    return v;
}

// ---- preprocessing ----
__global__ void k_zero(int N) {
    int i = blockIdx.x * blockDim.x + threadIdx.x;
    if (i < N) g_deg[i] = 0;
    if (i < 2) g_easum[i] = 0.f;
}

__global__ void k_easum(const float* __restrict__ EA, int E) {
    __shared__ float s0[256], s1[256];
    int tid = threadIdx.x;
    float a0 = 0.f, a1 = 0.f;
    for (int i = blockIdx.x * 256 + tid; i < E; i += gridDim.x * 256) {
        a0 += EA[2 * i];
        a1 += EA[2 * i + 1];
    }
    s0[tid] = a0; s1[tid] = a1;
    __syncthreads();
    for (int s = 128; s; s >>= 1) {
        if (tid < s) { s0[tid] += s0[tid + s]; s1[tid] += s1[tid + s]; }
        __syncthreads();
    }
    if (tid == 0) {
        atomicAdd(&g_easum[0], s0[0]);
        atomicAdd(&g_easum[1], s1[0]);
    }
}

__global__ void k_degree(const int* __restrict__ EI, int E, int EP) {
    int e = blockIdx.x * blockDim.x + threadIdx.x;
    if (e >= EP) return;
    int dst = (e < E) ? EI[E + e] : (e - E);
    atomicAdd(&g_deg[dst], 1);
}

// scan stage 1: block-local exclusive scan + block total
__global__ void k_scan1(int N) {
    __shared__ int sh[SCANB];
    int tid = threadIdx.x;
    int i = blockIdx.x * SCANB + tid;
    int v = (i < N) ? g_deg[i] : 0;
    sh[tid] = v;
    __syncthreads();
    for (int s = 1; s < SCANB; s <<= 1) {
        int t = (tid >= s) ? sh[tid - s] : 0;
        __syncthreads();
        sh[tid] += t;
        __syncthreads();
    }
    if (i < N) g_off[i] = sh[tid] - v;       // local exclusive
    if (tid == SCANB - 1) g_bsum[blockIdx.x] = sh[tid];
}

// scan stage 2: scan block sums (single warp, nb <= 64)
__global__ void k_scan2(int nb) {
    int tid = threadIdx.x;  // 64 threads
    int v = (tid < nb) ? g_bsum[tid] : 0;
    int x = v;
#pragma unroll
    for (int s = 1; s < 64; s <<= 1) {
        int t = __shfl_up_sync(0xffffffffu, x, s);
        if ((tid & 31) >= s) x += t;
    }
    __shared__ int w0;
    if (tid == 31) w0 = x;
    __syncthreads();
    if (tid >= 32) x += w0;
    if (tid < nb) g_bbase[tid] = x - v;      // exclusive
}

// scan stage 3: add block base, init cur, final total
__global__ void k_scan3(int N) {
    int i = blockIdx.x * blockDim.x + threadIdx.x;
    if (i > N) return;
    if (i == N) {
        g_off[N] = g_bbase[(N - 1) / SCANB] + g_bsum[(N - 1) / SCANB];
        return;
    }
    int o = g_off[i] + g_bbase[i / SCANB];
    g_off[i] = o;
    g_cur[i] = o;
}

__global__ void k_scatter(const int* __restrict__ EI, const float* __restrict__ EA,
                          int E, int EP, float invE) {
    int e = blockIdx.x * blockDim.x + threadIdx.x;
    if (e >= EP) return;
    int src, dst; float ea0, ea1;
    if (e < E) {
        src = EI[e]; dst = EI[E + e];
        ea0 = EA[2 * e]; ea1 = EA[2 * e + 1];
    } else {
        src = dst = e - E;
        ea0 = g_easum[0] * invE; ea1 = g_easum[1] * invE;
    }
    int pos = atomicAdd(&g_cur[dst], 1);
    g_srcOf[pos] = src;
    g_dstOf[pos] = dst;
    g_eas[pos] = make_float2(ea0, ea1);
}

// ---- node linears ----
__global__ void k_lin0(const float* __restrict__ x, const float* __restrict__ W0,
                       const float* __restrict__ b0, int N) {
    int i = blockIdx.x * blockDim.x + threadIdx.x;
    if (i >= N * HC) return;
    int n = i >> 6, j = i & 63;
    g_z[i] = fmaf(x[2 * n], W0[j], fmaf(x[2 * n + 1], W0[64 + j], b0[j]));
}

__global__ void k_lin64(const float* __restrict__ W, const float* __restrict__ b, int N) {
    __shared__ float sh[8][64];
    int gw = (blockIdx.x * blockDim.x + threadIdx.x) >> 5;
    int lane = threadIdx.x & 31;
    int wl = threadIdx.x >> 5;
    if (gw >= N) return;
    sh[wl][lane]      = g_hA[gw * 64 + lane];
    sh[wl][32 + lane] = g_hA[gw * 64 + 32 + lane];
    __syncwarp();
    float a0 = b[lane], a1 = b[32 + lane];
#pragma unroll
    for (int k = 0; k < 64; k++) {
        float hk = sh[wl][k];
        a0 = fmaf(hk, W[k * 64 + lane], a0);
        a1 = fmaf(hk, W[k * 64 + 32 + lane], a1);
    }
    g_z[gw * 64 + lane]      = a0;
    g_z[gw * 64 + 32 + lane] = a1;
}

// ---- phase 1: edge-parallel attention logits (warp per CSR slot) ----
__global__ void k_alpha(const float* __restrict__ We, const float* __restrict__ att,
                        int EP) {
    int gw = (blockIdx.x * blockDim.x + threadIdx.x) >> 5;
    int lane = threadIdx.x & 31;
    if (gw >= EP) return;
    int src = g_srcOf[gw];
    int dst = g_dstOf[gw];
    float2 ea = g_eas[gw];
    float zs0 = g_z[src * 64 + lane], zs1 = g_z[src * 64 + 32 + lane];
    float zd0 = g_z[dst * 64 + lane], zd1 = g_z[dst * 64 + 32 + lane];
    float t0 = zs0 + zd0 + ea.x * We[lane]      + ea.y * We[64 + lane];
    float t1 = zs1 + zd1 + ea.x * We[32 + lane] + ea.y * We[96 + lane];
    t0 = (t0 > 0.f) ? t0 : 0.2f * t0;
    t1 = (t1 > 0.f) ? t1 : 0.2f * t1;
    float a0 = warp_sum(t0 * att[lane]);
    float a1 = warp_sum(t1 * att[32 + lane]);
    if (lane == 0) g_al[gw] = make_float2(a0, a1);
}

// ---- phase 2: per-node softmax + aggregation + ELU (warp per node) ----
__global__ void k_gat2(const float* __restrict__ bias, int outSel, int N) {
    int gw = (blockIdx.x * blockDim.x + threadIdx.x) >> 5;
    int lane = threadIdx.x & 31;
    if (gw >= N) return;
    float* __restrict__ hout = outSel ? g_hB : g_hA;
    int d = gw;
    int off0 = g_off[d];
    int deg = g_off[d + 1] - off0;

    // max (coalesced strided)
    float m0 = -1e30f, m1 = -1e30f;
    for (int j = lane; j < deg; j += 32) {
        float2 al = g_al[off0 + j];
        m0 = fmaxf(m0, al.x);
        m1 = fmaxf(m1, al.y);
    }
    m0 = warp_max(m0);
    m1 = warp_max(m1);
    if (deg == 0) { m0 = 0.f; m1 = 0.f; }

    // denom
    float s0 = 0.f, s1 = 0.f;
    for (int j = lane; j < deg; j += 32) {
        float2 al = g_al[off0 + j];
        s0 += __expf(al.x - m0);
        s1 += __expf(al.y - m1);
    }
    s0 = warp_sum(s0);
    s1 = warp_sum(s1);
    float inv0 = 1.f / (s0 + 1e-16f);
    float inv1 = 1.f / (s1 + 1e-16f);

    // aggregation: manual unroll x4, loads hoisted
    float acc0 = 0.f, acc1 = 0.f;
    int j = 0;
    for (; j + 4 <= deg; j += 4) {
        int base = off0 + j;
        int sA = g_srcOf[base + 0];
        int sB = g_srcOf[base + 1];
        int sC = g_srcOf[base + 2];
        int sD = g_srcOf[base + 3];
        float2 aA = g_al[base + 0];
        float2 aB = g_al[base + 1];
        float2 aC = g_al[base + 2];
        float2 aD = g_al[base + 3];
        float zA0 = g_z[sA * 64 + lane], zA1 = g_z[sA * 64 + 32 + lane];
        float zB0 = g_z[sB * 64 + lane], zB1 = g_z[sB * 64 + 32 + lane];
        float zC0 = g_z[sC * 64 + lane], zC1 = g_z[sC * 64 + 32 + lane];
        float zD0 = g_z[sD * 64 + lane], zD1 = g_z[sD * 64 + 32 + lane];
        acc0 = fmaf(__expf(aA.x - m0) * inv0, zA0, acc0);
        acc1 = fmaf(__expf(aA.y - m1) * inv1, zA1, acc1);
        acc0 = fmaf(__expf(aB.x - m0) * inv0, zB0, acc0);
        acc1 = fmaf(__expf(aB.y - m1) * inv1, zB1, acc1);
        acc0 = fmaf(__expf(aC.x - m0) * inv0, zC0, acc0);
        acc1 = fmaf(__expf(aC.y - m1) * inv1, zC1, acc1);
        acc0 = fmaf(__expf(aD.x - m0) * inv0, zD0, acc0);
        acc1 = fmaf(__expf(aD.y - m1) * inv1, zD1, acc1);
    }
    for (; j < deg; j++) {
        int s = g_srcOf[off0 + j];
        float2 al = g_al[off0 + j];
        acc0 = fmaf(__expf(al.x - m0) * inv0, g_z[s * 64 + lane], acc0);
        acc1 = fmaf(__expf(al.y - m1) * inv1, g_z[s * 64 + 32 + lane], acc1);
    }
    float o0 = acc0 + bias[lane];
    float o1 = acc1 + bias[32 + lane];
    hout[d * 64 + lane]      = (o0 > 0.f) ? o0 : (__expf(o0) - 1.f);
    hout[d * 64 + 32 + lane] = (o1 > 0.f) ? o1 : (__expf(o1) - 1.f);
}

// ---- final edge MLP (factored) ----
__global__ void k_uv(const float* __restrict__ Wm1, int N) {
    __shared__ float sh[8][64];
    int gw = (blockIdx.x * blockDim.x + threadIdx.x) >> 5;
    int lane = threadIdx.x & 31;
    int wl = threadIdx.x >> 5;
    if (gw >= N) return;
    sh[wl][lane]      = g_hB[gw * 64 + lane];
    sh[wl][32 + lane] = g_hB[gw * 64 + 32 + lane];
    __syncwarp();
    float au = 0.f, av = 0.f;
#pragma unroll
    for (int k = 0; k < 64; k++) {
        float hk = sh[wl][k];
        au = fmaf(hk, Wm1[k * 32 + lane], au);
        av = fmaf(hk, Wm1[(64 + k) * 32 + lane], av);
    }
    g_u[gw * 32 + lane] = au;
    g_v[gw * 32 + lane] = av;
}

__global__ void k_goal(const float* __restrict__ Wm1, const float* __restrict__ bm1,
                       const int* __restrict__ dest) {
    int lane = threadIdx.x;
    int d = dest[0];
    float acc = bm1[lane];
    for (int k = 0; k < 64; k++)
        acc = fmaf(g_hB[d * 64 + k], Wm1[(128 + k) * 32 + lane], acc);
    g_gc[lane] = acc;
}

__global__ void k_edge(const int* __restrict__ EI, const float* __restrict__ EA,
                       const float* __restrict__ Wm1, const float* __restrict__ Wm2,
                       const float* __restrict__ bm2, float* __restrict__ out, int E) {
    int gw = (blockIdx.x * blockDim.x + threadIdx.x) >> 5;
    int lane = threadIdx.x & 31;
    if (gw >= E) return;
    int src = EI[gw], dst = EI[E + gw];
    float ea0 = EA[2 * gw], ea1 = EA[2 * gw + 1];
    float t = g_u[src * 32 + lane] + g_v[dst * 32 + lane] + g_gc[lane]
            + ea0 * Wm1[192 * 32 + lane] + ea1 * Wm1[193 * 32 + lane];
    t = fmaxf(t, 0.f);
    float p = warp_sum(t * Wm2[lane]);
    if (lane == 0) out[gw] = p + bm2[0];
}

extern "C" void kernel_launch(void* const* d_in, const int* in_sizes, int n_in,
                              void* d_out, int out_size) {
    const float* x     = (const float*)d_in[0];
    const int*   EI    = (const int*)  d_in[1];
    const float* EA    = (const float*)d_in[2];
    const int*   dest  = (const int*)  d_in[3];
    const float* W0    = (const float*)d_in[4];
    const float* b0    = (const float*)d_in[5];
    const float* We0   = (const float*)d_in[6];
    const float* att0  = (const float*)d_in[7];
    const float* bias0 = (const float*)d_in[8];
    const float* W1    = (const float*)d_in[9];
    const float* b1    = (const float*)d_in[10];
    const float* We1   = (const float*)d_in[11];
    const float* att1  = (const float*)d_in[12];
    const float* bias1 = (const float*)d_in[13];
    const float* Wm1   = (const float*)d_in[14];
    const float* bm1   = (const float*)d_in[15];
    const float* Wm2   = (const float*)d_in[16];
    const float* bm2   = (const float*)d_in[17];

    int N  = in_sizes[0] / 2;
    int E  = in_sizes[1] / 2;
    int EP = E + N;
    int nb = (N + SCANB - 1) / SCANB;
    float invE = 1.0f / (float)E;
    float* out = (float*)d_out;

    // CSR build
    k_zero   <<<(N + 255) / 256, 256>>>(N);
    k_easum  <<<512, 256>>>(EA, E);
    k_degree <<<(EP + 255) / 256, 256>>>(EI, E, EP);
    k_scan1  <<<nb, SCANB>>>(N);
    k_scan2  <<<1, 64>>>(nb);
    k_scan3  <<<(N + 256) / 256, 256>>>(N);
    k_scatter<<<(EP + 255) / 256, 256>>>(EI, EA, E, EP, invE);

    int nodeBlocks = (N + 7) / 8;
    int slotBlocks = (EP + 7) / 8;

    // layer 0
    k_lin0 <<<(N * 64 + 255) / 256, 256>>>(x, W0, b0, N);
    k_alpha<<<slotBlocks, 256>>>(We0, att0, EP);
    k_gat2 <<<nodeBlocks, 256>>>(bias0, /*outSel=*/0, N);

    // layer 1
    k_lin64<<<nodeBlocks, 256>>>(W1, b1, N);
    k_alpha<<<slotBlocks, 256>>>(We1, att1, EP);
    k_gat2 <<<nodeBlocks, 256>>>(bias1, /*outSel=*/1, N);

    // edge MLP
    k_uv   <<<nodeBlocks, 256>>>(Wm1, N);
    k_goal <<<1, 32>>>(Wm1, bm1, dest);
    k_edge <<<(E + 7) / 8, 256>>>(EI, EA, Wm1, Wm2, bm2, out, E);
}

// round 3
// speedup vs baseline: 1.7321x; 1.5097x over previous
#include <cuda_runtime.h>
#include <math.h>

// 2-layer GATv2 (H=2 heads, C=32 ch) + edge MLP.
// N=50000 nodes, E=800000 edges (+N self loops). Output: E float logits.

#define HC 64
#define CC 32
#define MAXN 65536
#define MAXE 1048576
#define MAXEP (MAXE + MAXN)
#define SCANB 1024
#define MAXBLK 64

// ---- device scratch (static) ----
__device__ float  g_z[MAXN * HC];
__device__ float  g_hA[MAXN * HC];
__device__ float  g_hB[MAXN * HC];
__device__ int    g_deg[MAXN];
__device__ int    g_off[MAXN + 1];
__device__ int    g_cur[MAXN];
__device__ int    g_srcOf[MAXEP];
__device__ int    g_dstOf[MAXEP];
__device__ float2 g_eas[MAXEP];
__device__ float2 g_al[MAXEP];
__device__ float  g_u[MAXN * CC];
__device__ float  g_v[MAXN * CC];
__device__ float  g_easum[2];
__device__ float  g_gc[CC];
__device__ int    g_bsum[MAXBLK];
__device__ int    g_bbase[MAXBLK];

__device__ __forceinline__ float warp_max(float v) {
#pragma unroll
    for (int o = 16; o; o >>= 1) v = fmaxf(v, __shfl_xor_sync(0xffffffffu, v, o));
    return v;
}

// ---- preprocessing ----
__global__ void k_zero(int N) {
    int i = blockIdx.x * blockDim.x + threadIdx.x;
    if (i < N) g_deg[i] = 0;
    if (i < 2) g_easum[i] = 0.f;
}

// fused: degree count (real edges) + edge_attr column sums
__global__ void k_deg_ea(const int* __restrict__ EI, const float* __restrict__ EA, int E) {
    __shared__ float s0[256], s1[256];
    int tid = threadIdx.x;
    float a0 = 0.f, a1 = 0.f;
    for (int e = blockIdx.x * 256 + tid; e < E; e += gridDim.x * 256) {
        atomicAdd(&g_deg[EI[E + e]], 1);
        float2 ea = ((const float2*)EA)[e];
        a0 += ea.x; a1 += ea.y;
    }
    s0[tid] = a0; s1[tid] = a1;
    __syncthreads();
    for (int s = 128; s; s >>= 1) {
        if (tid < s) { s0[tid] += s0[tid + s]; s1[tid] += s1[tid + s]; }
        __syncthreads();
    }
    if (tid == 0) {
        atomicAdd(&g_easum[0], s0[0]);
        atomicAdd(&g_easum[1], s1[0]);
    }
}

// scan stage 1: block-local exclusive scan (degree + 1 self loop per node)
__global__ void k_scan1(int N) {
    __shared__ int sh[SCANB];
    int tid = threadIdx.x;
    int i = blockIdx.x * SCANB + tid;
    int v = (i < N) ? g_deg[i] + 1 : 0;
    sh[tid] = v;
    __syncthreads();
    for (int s = 1; s < SCANB; s <<= 1) {
        int t = (tid >= s) ? sh[tid - s] : 0;
        __syncthreads();
        sh[tid] += t;
        __syncthreads();
    }
    if (i < N) g_off[i] = sh[tid] - v;
    if (tid == SCANB - 1) g_bsum[blockIdx.x] = sh[tid];
}

__global__ void k_scan2(int nb) {
    int tid = threadIdx.x;  // 64 threads
    int v = (tid < nb) ? g_bsum[tid] : 0;
    int x = v;
#pragma unroll
    for (int s = 1; s < 32; s <<= 1) {
        int t = __shfl_up_sync(0xffffffffu, x, s);
        if ((tid & 31) >= s) x += t;
    }
    __shared__ int w0;
    if (tid == 31) w0 = x;
    __syncthreads();
    if (tid >= 32) x += w0;
    if (tid < nb) g_bbase[tid] = x - v;
}

// scan stage 3: finalize offsets, init cur, place self-loop slot at end of segment
__global__ void k_scan3(int N, float invE) {
    int i = blockIdx.x * blockDim.x + threadIdx.x;
    if (i > N) return;
    int nb = (N + SCANB - 1) / SCANB;
    if (i == N) {
        g_off[N] = g_bbase[nb - 1] + g_bsum[nb - 1];
        return;
    }
    int o = g_off[i] + g_bbase[i / SCANB];
    g_off[i] = o;
    g_cur[i] = o;
    int slot = o + g_deg[i];             // last slot of segment = self loop
    g_srcOf[slot] = i;
    g_dstOf[slot] = i;
    g_eas[slot] = make_float2(g_easum[0] * invE, g_easum[1] * invE);
}

__global__ void k_scatter(const int* __restrict__ EI, const float* __restrict__ EA, int E) {
    int e = blockIdx.x * blockDim.x + threadIdx.x;
    if (e >= E) return;
    int src = EI[e], dst = EI[E + e];
    int pos = atomicAdd(&g_cur[dst], 1);
    g_srcOf[pos] = src;
    g_dstOf[pos] = dst;
    g_eas[pos] = ((const float2*)EA)[e];
}

// ---- node linears ----
__global__ void k_lin0(const float* __restrict__ x, const float* __restrict__ W0,
                       const float* __restrict__ b0, int N) {
    int i = blockIdx.x * blockDim.x + threadIdx.x;
    if (i >= N * HC) return;
    int n = i >> 6, j = i & 63;
    g_z[i] = fmaf(x[2 * n], W0[j], fmaf(x[2 * n + 1], W0[64 + j], b0[j]));
}

__global__ void k_lin64(const float* __restrict__ W, const float* __restrict__ b, int N) {
    __shared__ float sh[8][64];
    int gw = (blockIdx.x * blockDim.x + threadIdx.x) >> 5;
    int lane = threadIdx.x & 31;
    int wl = threadIdx.x >> 5;
    if (gw >= N) return;
    sh[wl][lane]      = g_hA[gw * 64 + lane];
    sh[wl][32 + lane] = g_hA[gw * 64 + 32 + lane];
    __syncwarp();
    float a0 = b[lane], a1 = b[32 + lane];
#pragma unroll
    for (int k = 0; k < 64; k++) {
        float hk = sh[wl][k];
        a0 = fmaf(hk, W[k * 64 + lane], a0);
        a1 = fmaf(hk, W[k * 64 + 32 + lane], a1);
    }
    g_z[gw * 64 + lane]      = a0;
    g_z[gw * 64 + 32 + lane] = a1;
}

// ---- phase 1: attention logits, 2 slots per warp, float4 channel lanes ----
__global__ void k_alpha(const float* __restrict__ We, const float* __restrict__ att,
                        int EP) {
    int warpId = (blockIdx.x * blockDim.x + threadIdx.x) >> 5;
    int lane = threadIdx.x & 31;
    int sub = lane & 15;                 // channel group: 4 channels each
    if (warpId * 2 >= EP) return;
    int sl = warpId * 2 + (lane >> 4);
    if (sl >= EP) sl = EP - 1;           // duplicate work, benign dup write

    float4 att4 = ((const float4*)att)[sub];
    float4 weA  = ((const float4*)We)[sub];        // We row 0 (ea.x)
    float4 weB  = ((const float4*)We)[16 + sub];   // We row 1 (ea.y)

    int src = g_srcOf[sl];
    int dst = g_dstOf[sl];
    float2 ea = g_eas[sl];
    float4 zs = ((const float4*)g_z)[src * 16 + sub];
    float4 zd = ((const float4*)g_z)[dst * 16 + sub];

    float4 t;
    t.x = zs.x + zd.x + ea.x * weA.x + ea.y * weB.x;
    t.y = zs.y + zd.y + ea.x * weA.y + ea.y * weB.y;
    t.z = zs.z + zd.z + ea.x * weA.z + ea.y * weB.z;
    t.w = zs.w + zd.w + ea.x * weA.w + ea.y * weB.w;
    t.x = (t.x > 0.f) ? t.x : 0.2f * t.x;
    t.y = (t.y > 0.f) ? t.y : 0.2f * t.y;
    t.z = (t.z > 0.f) ? t.z : 0.2f * t.z;
    t.w = (t.w > 0.f) ? t.w : 0.2f * t.w;

    float p = t.x * att4.x + t.y * att4.y + t.z * att4.z + t.w * att4.w;
    p += __shfl_xor_sync(0xffffffffu, p, 1);
    p += __shfl_xor_sync(0xffffffffu, p, 2);
    p += __shfl_xor_sync(0xffffffffu, p, 4);
    float other = __shfl_xor_sync(0xffffffffu, p, 8);   // head1 partial to sub==0
    if (sub == 0) g_al[sl] = make_float2(p, other);
}

// ---- phase 2: per-node softmax + aggregation + ELU (warp per node) ----
// lanes hold float2 channels; lanes 0-15 = head0, 16-31 = head1.
// Normalization folded to the end: acc = sum(w*z); s accumulated redundantly per lane.
__global__ void k_gat2(const float* __restrict__ bias, int outSel, int N) {
    int d = (blockIdx.x * blockDim.x + threadIdx.x) >> 5;
    int lane = threadIdx.x & 31;
    if (d >= N) return;
    float* __restrict__ hout = outSel ? g_hB : g_hA;
    int off0 = g_off[d];
    int deg = g_off[d + 1] - off0;       // >= 1 (self loop)

    // pass 1: segment max per head
    float m0 = -1e30f, m1 = -1e30f;
    for (int j = lane; j < deg; j += 32) {
        float2 al = g_al[off0 + j];
        m0 = fmaxf(m0, al.x);
        m1 = fmaxf(m1, al.y);
    }
    m0 = warp_max(m0);
    m1 = warp_max(m1);
    float m = (lane < 16) ? m0 : m1;

    // pass 2: unnormalized aggregation + per-lane denom
    const float2* __restrict__ z2 = (const float2*)g_z;
    float2 acc = make_float2(0.f, 0.f);
    float s = 0.f;
    int j = 0;
    for (; j + 4 <= deg; j += 4) {
        int b = off0 + j;
        int sA = g_srcOf[b + 0];
        int sB = g_srcOf[b + 1];
        int sC = g_srcOf[b + 2];
        int sD = g_srcOf[b + 3];
        float2 aA = g_al[b + 0];
        float2 aB = g_al[b + 1];
        float2 aC = g_al[b + 2];
        float2 aD = g_al[b + 3];
        float2 zA = z2[sA * 32 + lane];
        float2 zB = z2[sB * 32 + lane];
        float2 zC = z2[sC * 32 + lane];
        float2 zD = z2[sD * 32 + lane];
        float wA = __expf(((lane < 16) ? aA.x : aA.y) - m);
        float wB = __expf(((lane < 16) ? aB.x : aB.y) - m);
        float wC = __expf(((lane < 16) ? aC.x : aC.y) - m);
        float wD = __expf(((lane < 16) ? aD.x : aD.y) - m);
        s += wA + wB + wC + wD;
        acc.x = fmaf(wA, zA.x, acc.x); acc.y = fmaf(wA, zA.y, acc.y);
        acc.x = fmaf(wB, zB.x, acc.x); acc.y = fmaf(wB, zB.y, acc.y);
        acc.x = fmaf(wC, zC.x, acc.x); acc.y = fmaf(wC, zC.y, acc.y);
        acc.x = fmaf(wD, zD.x, acc.x); acc.y = fmaf(wD, zD.y, acc.y);
    }
    for (; j < deg; j++) {
        int sE = g_srcOf[off0 + j];
        float2 al = g_al[off0 + j];
        float2 zE = z2[sE * 32 + lane];
        float w = __expf(((lane < 16) ? al.x : al.y) - m);
        s += w;
        acc.x = fmaf(w, zE.x, acc.x);
        acc.y = fmaf(w, zE.y, acc.y);
    }
    float inv = 1.f / (s + 1e-16f);
    float2 bias2 = ((const float2*)bias)[lane];
    float o0 = acc.x * inv + bias2.x;
    float o1 = acc.y * inv + bias2.y;
    o0 = (o0 > 0.f) ? o0 : (__expf(o0) - 1.f);
    o1 = (o1 > 0.f) ? o1 : (__expf(o1) - 1.f);
    ((float2*)hout)[d * 32 + lane] = make_float2(o0, o1);
}

// ---- final edge MLP (factored) ----
__global__ void k_uv(const float* __restrict__ Wm1, int N) {
    __shared__ float sh[8][64];
    int gw = (blockIdx.x * blockDim.x + threadIdx.x) >> 5;
    int lane = threadIdx.x & 31;
    int wl = threadIdx.x >> 5;
    if (gw >= N) return;
    sh[wl][lane]      = g_hB[gw * 64 + lane];
    sh[wl][32 + lane] = g_hB[gw * 64 + 32 + lane];
    __syncwarp();
    float au = 0.f, av = 0.f;
#pragma unroll
    for (int k = 0; k < 64; k++) {
        float hk = sh[wl][k];
        au = fmaf(hk, Wm1[k * 32 + lane], au);
        av = fmaf(hk, Wm1[(64 + k) * 32 + lane], av);
    }
    g_u[gw * 32 + lane] = au;
    g_v[gw * 32 + lane] = av;
}

__global__ void k_goal(const float* __restrict__ Wm1, const float* __restrict__ bm1,
                       const int* __restrict__ dest) {
    int lane = threadIdx.x;
    int d = dest[0];
    float acc = bm1[lane];
    for (int k = 0; k < 64; k++)
        acc = fmaf(g_hB[d * 64 + k], Wm1[(128 + k) * 32 + lane], acc);
    g_gc[lane] = acc;
}

// 2 edges per warp, float2 channel lanes
__global__ void k_edge(const int* __restrict__ EI, const float* __restrict__ EA,
                       const float* __restrict__ Wm1, const float* __restrict__ Wm2,
                       const float* __restrict__ bm2, float* __restrict__ out, int E) {
    int warpId = (blockIdx.x * blockDim.x + threadIdx.x) >> 5;
    int lane = threadIdx.x & 31;
    int sub = lane & 15;
    if (warpId * 2 >= E) return;
    int e = warpId * 2 + (lane >> 4);
    bool valid = (e < E);
    if (!valid) e = E - 1;

    int src = EI[e], dst = EI[E + e];
    float2 ea = ((const float2*)EA)[e];
    float2 u2 = ((const float2*)g_u)[src * 16 + sub];
    float2 v2 = ((const float2*)g_v)[dst * 16 + sub];
    float2 gc2 = ((const float2*)g_gc)[sub];
    float2 wa  = ((const float2*)(Wm1 + 192 * 32))[sub];
    float2 wb  = ((const float2*)(Wm1 + 193 * 32))[sub];
    float2 wm2 = ((const float2*)Wm2)[sub];

    float t0 = u2.x + v2.x + gc2.x + ea.x * wa.x + ea.y * wb.x;
    float t1 = u2.y + v2.y + gc2.y + ea.x * wa.y + ea.y * wb.y;
    t0 = fmaxf(t0, 0.f);
    t1 = fmaxf(t1, 0.f);
    float p = t0 * wm2.x + t1 * wm2.y;
    p += __shfl_xor_sync(0xffffffffu, p, 1);
    p += __shfl_xor_sync(0xffffffffu, p, 2);
    p += __shfl_xor_sync(0xffffffffu, p, 4);
    p += __shfl_xor_sync(0xffffffffu, p, 8);
    if (sub == 0 && valid) out[e] = p + __ldg(bm2);
}

extern "C" void kernel_launch(void* const* d_in, const int* in_sizes, int n_in,
                              void* d_out, int out_size) {
    const float* x     = (const float*)d_in[0];
    const int*   EI    = (const int*)  d_in[1];
    const float* EA    = (const float*)d_in[2];
    const int*   dest  = (const int*)  d_in[3];
    const float* W0    = (const float*)d_in[4];
    const float* b0    = (const float*)d_in[5];
    const float* We0   = (const float*)d_in[6];
    const float* att0  = (const float*)d_in[7];
    const float* bias0 = (const float*)d_in[8];
    const float* W1    = (const float*)d_in[9];
    const float* b1    = (const float*)d_in[10];
    const float* We1   = (const float*)d_in[11];
    const float* att1  = (const float*)d_in[12];
    const float* bias1 = (const float*)d_in[13];
    const float* Wm1   = (const float*)d_in[14];
    const float* bm1   = (const float*)d_in[15];
    const float* Wm2   = (const float*)d_in[16];
    const float* bm2   = (const float*)d_in[17];

    int N  = in_sizes[0] / 2;
    int E  = in_sizes[1] / 2;
    int EP = E + N;
    int nb = (N + SCANB - 1) / SCANB;
    float invE = 1.0f / (float)E;
    float* out = (float*)d_out;

    // CSR build
    k_zero   <<<(N + 255) / 256, 256>>>(N);
    k_deg_ea <<<512, 256>>>(EI, EA, E);
    k_scan1  <<<nb, SCANB>>>(N);
    k_scan2  <<<1, 64>>>(nb);
    k_scan3  <<<(N + 256) / 256, 256>>>(N, invE);
    k_scatter<<<(E + 255) / 256, 256>>>(EI, EA, E);

    int nodeBlocks = (N + 7) / 8;
    int slotBlocks = (EP + 15) / 16;     // 2 slots per warp, 8 warps per block

    // layer 0
    k_lin0 <<<(N * 64 + 255) / 256, 256>>>(x, W0, b0, N);
    k_alpha<<<slotBlocks, 256>>>(We0, att0, EP);
    k_gat2 <<<nodeBlocks, 256>>>(bias0, /*outSel=*/0, N);

    // layer 1
    k_lin64<<<nodeBlocks, 256>>>(W1, b1, N);
    k_alpha<<<slotBlocks, 256>>>(We1, att1, EP);
    k_gat2 <<<nodeBlocks, 256>>>(bias1, /*outSel=*/1, N);

    // edge MLP
    k_uv   <<<nodeBlocks, 256>>>(Wm1, N);
    k_goal <<<1, 32>>>(Wm1, bm1, dest);
    k_edge <<<(E + 15) / 16, 256>>>(EI, EA, Wm1, Wm2, bm2, out, E);
}

// round 4
// speedup vs baseline: 2.1254x; 1.2271x over previous
#include <cuda_runtime.h>
#include <math.h>

// 2-layer GATv2 (H=2 heads, C=32 ch) + edge MLP.
// N=50000 nodes, E=800000 edges (+N self loops). Output: E float logits.

#define HC 64
#define CC 32
#define MAXN 65536
#define MAXE 1048576
#define MAXEP (MAXE + MAXN)
#define SCANB 1024
#define MAXBLK 64

// ---- device scratch (static) ----
__device__ float  g_z[MAXN * HC];
__device__ float  g_hA[MAXN * HC];
__device__ float  g_hB[MAXN * HC];
__device__ int    g_deg[MAXN];
__device__ int    g_off[MAXN + 1];
__device__ int    g_cur[MAXN];
__device__ int    g_srcOf[MAXEP];
__device__ float2 g_eas[MAXEP];
__device__ float  g_u[MAXN * CC];
__device__ float  g_v[MAXN * CC];
__device__ float  g_easum[2];
__device__ float  g_gc[CC];
__device__ int    g_bsum[MAXBLK];
__device__ int    g_bbase[MAXBLK];

// ---- preprocessing ----
__global__ void k_zero(int N) {
    int i = blockIdx.x * blockDim.x + threadIdx.x;
    if (i < N) g_deg[i] = 0;
    if (i < 2) g_easum[i] = 0.f;
}

// fused: degree count (real edges) + edge_attr column sums
__global__ void k_deg_ea(const int* __restrict__ EI, const float* __restrict__ EA, int E) {
    __shared__ float s0[256], s1[256];
    int tid = threadIdx.x;
    float a0 = 0.f, a1 = 0.f;
    for (int e = blockIdx.x * 256 + tid; e < E; e += gridDim.x * 256) {
        atomicAdd(&g_deg[EI[E + e]], 1);
        float2 ea = ((const float2*)EA)[e];
        a0 += ea.x; a1 += ea.y;
    }
    s0[tid] = a0; s1[tid] = a1;
    __syncthreads();
    for (int s = 128; s; s >>= 1) {
        if (tid < s) { s0[tid] += s0[tid + s]; s1[tid] += s1[tid + s]; }
        __syncthreads();
    }
    if (tid == 0) {
        atomicAdd(&g_easum[0], s0[0]);
        atomicAdd(&g_easum[1], s1[0]);
    }
}

// scan stage 1: block-local exclusive scan (degree + 1 self loop per node)
__global__ void k_scan1(int N) {
    __shared__ int sh[SCANB];
    int tid = threadIdx.x;
    int i = blockIdx.x * SCANB + tid;
    int v = (i < N) ? g_deg[i] + 1 : 0;
    sh[tid] = v;
    __syncthreads();
    for (int s = 1; s < SCANB; s <<= 1) {
        int t = (tid >= s) ? sh[tid - s] : 0;
        __syncthreads();
        sh[tid] += t;
        __syncthreads();
    }
    if (i < N) g_off[i] = sh[tid] - v;
    if (tid == SCANB - 1) g_bsum[blockIdx.x] = sh[tid];
}

__global__ void k_scan2(int nb) {
    int tid = threadIdx.x;  // 64 threads
    int v = (tid < nb) ? g_bsum[tid] : 0;
    int x = v;
#pragma unroll
    for (int s = 1; s < 32; s <<= 1) {
        int t = __shfl_up_sync(0xffffffffu, x, s);
        if ((tid & 31) >= s) x += t;
    }
    __shared__ int w0;
    if (tid == 31) w0 = x;
    __syncthreads();
    if (tid >= 32) x += w0;
    if (tid < nb) g_bbase[tid] = x - v;
}

// scan stage 3: finalize offsets, init cur, place self-loop slot at end of segment
__global__ void k_scan3(int N, float invE) {
    int i = blockIdx.x * blockDim.x + threadIdx.x;
    if (i > N) return;
    int nb = (N + SCANB - 1) / SCANB;
    if (i == N) {
        g_off[N] = g_bbase[nb - 1] + g_bsum[nb - 1];
        return;
    }
    int o = g_off[i] + g_bbase[i / SCANB];
    g_off[i] = o;
    g_cur[i] = o;
    int slot = o + g_deg[i];             // last slot of segment = self loop
    g_srcOf[slot] = i;
    g_eas[slot] = make_float2(g_easum[0] * invE, g_easum[1] * invE);
}

__global__ void k_scatter(const int* __restrict__ EI, const float* __restrict__ EA, int E) {
    int e = blockIdx.x * blockDim.x + threadIdx.x;
    if (e >= E) return;
    int dst = EI[E + e];
    int pos = atomicAdd(&g_cur[dst], 1);
    g_srcOf[pos] = EI[e];
    g_eas[pos] = ((const float2*)EA)[e];
}

// ---- node linears ----
__global__ void k_lin0(const float* __restrict__ x, const float* __restrict__ W0,
                       const float* __restrict__ b0, int N) {
    int i = blockIdx.x * blockDim.x + threadIdx.x;
    if (i >= N * HC) return;
    int n = i >> 6, j = i & 63;
    g_z[i] = fmaf(x[2 * n], W0[j], fmaf(x[2 * n + 1], W0[64 + j], b0[j]));
}

__global__ void k_lin64(const float* __restrict__ W, const float* __restrict__ b, int N) {
    __shared__ float sh[8][64];
    int gw = (blockIdx.x * blockDim.x + threadIdx.x) >> 5;
    int lane = threadIdx.x & 31;
    int wl = threadIdx.x >> 5;
    if (gw >= N) return;
    sh[wl][lane]      = g_hA[gw * 64 + lane];
    sh[wl][32 + lane] = g_hA[gw * 64 + 32 + lane];
    __syncwarp();
    float a0 = b[lane], a1 = b[32 + lane];
#pragma unroll
    for (int k = 0; k < 64; k++) {
        float hk = sh[wl][k];
        a0 = fmaf(hk, W[k * 64 + lane], a0);
        a1 = fmaf(hk, W[k * 64 + 32 + lane], a1);
    }
    g_z[gw * 64 + lane]      = a0;
    g_z[gw * 64 + 32 + lane] = a1;
}

// ---- fused GATv2: logits + online softmax + aggregation + ELU ----
// warp per destination node. Lanes hold float2 channels:
// lanes 0-15 = head0 (ch 0-31), lanes 16-31 = head1 (ch 32-63).
// One z[src] gather per slot (online softmax rescaling).
__global__ void k_gatF(const float* __restrict__ We, const float* __restrict__ att,
                       const float* __restrict__ bias, int outSel, int N) {
    int d = (blockIdx.x * blockDim.x + threadIdx.x) >> 5;
    int lane = threadIdx.x & 31;
    if (d >= N) return;
    float* __restrict__ hout = outSel ? g_hB : g_hA;
    const float2* __restrict__ z2 = (const float2*)g_z;

    int off0 = g_off[d];
    int deg = g_off[d + 1] - off0;       // >= 1 (self loop)

    // per-lane constants: this lane's 2 channels of its head
    // channel index within g_z row: lane*2, lane*2+1  (head = lane/16)
    float2 zd   = z2[d * 32 + lane];
    float2 we0  = make_float2(We[lane * 2],      We[lane * 2 + 1]);       // row ea.x
    float2 we1  = make_float2(We[64 + lane * 2], We[64 + lane * 2 + 1]);  // row ea.y
    float2 at   = make_float2(att[lane * 2],     att[lane * 2 + 1]);

    float m = -1e30f, s = 0.f;
    float2 acc = make_float2(0.f, 0.f);

    int j = 0;
    for (; j + 2 <= deg; j += 2) {
        int b = off0 + j;
        int s1 = g_srcOf[b];
        int s2 = g_srcOf[b + 1];
        float2 e1 = g_eas[b];
        float2 e2 = g_eas[b + 1];
        float2 za = z2[s1 * 32 + lane];
        float2 zb = z2[s2 * 32 + lane];

        float t1x = zd.x + za.x + e1.x * we0.x + e1.y * we1.x;
        float t1y = zd.y + za.y + e1.x * we0.y + e1.y * we1.y;
        float t2x = zd.x + zb.x + e2.x * we0.x + e2.y * we1.x;
        float t2y = zd.y + zb.y + e2.x * we0.y + e2.y * we1.y;
        t1x = (t1x > 0.f) ? t1x : 0.2f * t1x;
        t1y = (t1y > 0.f) ? t1y : 0.2f * t1y;
        t2x = (t2x > 0.f) ? t2x : 0.2f * t2x;
        t2y = (t2y > 0.f) ? t2y : 0.2f * t2y;

        float a1 = t1x * at.x + t1y * at.y;
        float a2 = t2x * at.x + t2y * at.y;
        // reduce within 16-lane half (reduces head0 and head1 simultaneously)
#pragma unroll
        for (int o = 1; o < 16; o <<= 1) {
            a1 += __shfl_xor_sync(0xffffffffu, a1, o);
            a2 += __shfl_xor_sync(0xffffffffu, a2, o);
        }

        float M = fmaxf(m, fmaxf(a1, a2));
        float sc = __expf(m - M);
        float w1 = __expf(a1 - M);
        float w2 = __expf(a2 - M);
        s = s * sc + w1 + w2;
        acc.x = acc.x * sc + w1 * za.x + w2 * zb.x;
        acc.y = acc.y * sc + w1 * za.y + w2 * zb.y;
        m = M;
    }
    if (j < deg) {
        int b = off0 + j;
        int s1 = g_srcOf[b];
        float2 e1 = g_eas[b];
        float2 za = z2[s1 * 32 + lane];
        float t1x = zd.x + za.x + e1.x * we0.x + e1.y * we1.x;
        float t1y = zd.y + za.y + e1.x * we0.y + e1.y * we1.y;
        t1x = (t1x > 0.f) ? t1x : 0.2f * t1x;
        t1y = (t1y > 0.f) ? t1y : 0.2f * t1y;
        float a1 = t1x * at.x + t1y * at.y;
#pragma unroll
        for (int o = 1; o < 16; o <<= 1)
            a1 += __shfl_xor_sync(0xffffffffu, a1, o);
        float M = fmaxf(m, a1);
        float sc = __expf(m - M);
        float w1 = __expf(a1 - M);
        s = s * sc + w1;
        acc.x = acc.x * sc + w1 * za.x;
        acc.y = acc.y * sc + w1 * za.y;
    }

    float inv = 1.f / (s + 1e-16f);
    float2 bias2 = ((const float2*)bias)[lane];
    float o0 = acc.x * inv + bias2.x;
    float o1 = acc.y * inv + bias2.y;
    o0 = (o0 > 0.f) ? o0 : (__expf(o0) - 1.f);
    o1 = (o1 > 0.f) ? o1 : (__expf(o1) - 1.f);
    ((float2*)hout)[d * 32 + lane] = make_float2(o0, o1);
}

// ---- final edge MLP (factored) ----
__global__ void k_uv(const float* __restrict__ Wm1, int N) {
    __shared__ float sh[8][64];
    int gw = (blockIdx.x * blockDim.x + threadIdx.x) >> 5;
    int lane = threadIdx.x & 31;
    int wl = threadIdx.x >> 5;
    if (gw >= N) return;
    sh[wl][lane]      = g_hB[gw * 64 + lane];
    sh[wl][32 + lane] = g_hB[gw * 64 + 32 + lane];
    __syncwarp();
    float au = 0.f, av = 0.f;
#pragma unroll
    for (int k = 0; k < 64; k++) {
        float hk = sh[wl][k];
        au = fmaf(hk, Wm1[k * 32 + lane], au);
        av = fmaf(hk, Wm1[(64 + k) * 32 + lane], av);
    }
    g_u[gw * 32 + lane] = au;
    g_v[gw * 32 + lane] = av;
}

__global__ void k_goal(const float* __restrict__ Wm1, const float* __restrict__ bm1,
                       const int* __restrict__ dest) {
    int lane = threadIdx.x;
    int d = dest[0];
    float acc = bm1[lane];
    for (int k = 0; k < 64; k++)
        acc = fmaf(g_hB[d * 64 + k], Wm1[(128 + k) * 32 + lane], acc);
    g_gc[lane] = acc;
}

// 2 edges per warp, float2 channel lanes
__global__ void k_edge(const int* __restrict__ EI, const float* __restrict__ EA,
                       const float* __restrict__ Wm1, const float* __restrict__ Wm2,
                       const float* __restrict__ bm2, float* __restrict__ out, int E) {
    int warpId = (blockIdx.x * blockDim.x + threadIdx.x) >> 5;
    int lane = threadIdx.x & 31;
    int sub = lane & 15;
    if (warpId * 2 >= E) return;
    int e = warpId * 2 + (lane >> 4);
    bool valid = (e < E);
    if (!valid) e = E - 1;

    int src = EI[e], dst = EI[E + e];
    float2 ea = ((const float2*)EA)[e];
    float2 u2 = ((const float2*)g_u)[src * 16 + sub];
    float2 v2 = ((const float2*)g_v)[dst * 16 + sub];
    float2 gc2 = ((const float2*)g_gc)[sub];
    float2 wa  = ((const float2*)(Wm1 + 192 * 32))[sub];
    float2 wb  = ((const float2*)(Wm1 + 193 * 32))[sub];
    float2 wm2 = ((const float2*)Wm2)[sub];

    float t0 = u2.x + v2.x + gc2.x + ea.x * wa.x + ea.y * wb.x;
    float t1 = u2.y + v2.y + gc2.y + ea.x * wa.y + ea.y * wb.y;
    t0 = fmaxf(t0, 0.f);
    t1 = fmaxf(t1, 0.f);
    float p = t0 * wm2.x + t1 * wm2.y;
    p += __shfl_xor_sync(0xffffffffu, p, 1);
    p += __shfl_xor_sync(0xffffffffu, p, 2);
    p += __shfl_xor_sync(0xffffffffu, p, 4);
    p += __shfl_xor_sync(0xffffffffu, p, 8);
    if (sub == 0 && valid) out[e] = p + __ldg(bm2);
}

extern "C" void kernel_launch(void* const* d_in, const int* in_sizes, int n_in,
                              void* d_out, int out_size) {
    const float* x     = (const float*)d_in[0];
    const int*   EI    = (const int*)  d_in[1];
    const float* EA    = (const float*)d_in[2];
    const int*   dest  = (const int*)  d_in[3];
    const float* W0    = (const float*)d_in[4];
    const float* b0    = (const float*)d_in[5];
    const float* We0   = (const float*)d_in[6];
    const float* att0  = (const float*)d_in[7];
    const float* bias0 = (const float*)d_in[8];
    const float* W1    = (const float*)d_in[9];
    const float* b1    = (const float*)d_in[10];
    const float* We1   = (const float*)d_in[11];
    const float* att1  = (const float*)d_in[12];
    const float* bias1 = (const float*)d_in[13];
    const float* Wm1   = (const float*)d_in[14];
    const float* bm1   = (const float*)d_in[15];
    const float* Wm2   = (const float*)d_in[16];
    const float* bm2   = (const float*)d_in[17];

    int N  = in_sizes[0] / 2;
    int E  = in_sizes[1] / 2;
    int nb = (N + SCANB - 1) / SCANB;
    float invE = 1.0f / (float)E;
    float* out = (float*)d_out;

    // CSR build
    k_zero   <<<(N + 255) / 256, 256>>>(N);
    k_deg_ea <<<512, 256>>>(EI, EA, E);
    k_scan1  <<<nb, SCANB>>>(N);
    k_scan2  <<<1, 64>>>(nb);
    k_scan3  <<<(N + 256) / 256, 256>>>(N, invE);
    k_scatter<<<(E + 255) / 256, 256>>>(EI, EA, E);

    int nodeBlocks = (N + 7) / 8;

    // layer 0
    k_lin0 <<<(N * 64 + 255) / 256, 256>>>(x, W0, b0, N);
    k_gatF <<<nodeBlocks, 256>>>(We0, att0, bias0, /*outSel=*/0, N);

    // layer 1
    k_lin64<<<nodeBlocks, 256>>>(W1, b1, N);
    k_gatF <<<nodeBlocks, 256>>>(We1, att1, bias1, /*outSel=*/1, N);

    // edge MLP
    k_uv   <<<nodeBlocks, 256>>>(Wm1, N);
    k_goal <<<1, 32>>>(Wm1, bm1, dest);
    k_edge <<<(E + 15) / 16, 256>>>(EI, EA, Wm1, Wm2, bm2, out, E);
}